// round 1
// baseline (speedup 1.0000x reference)
#include <cuda_runtime.h>

#define NMAX 100000

// Scratch: h = X @ W  (25.6 MB static device array — allocation-free)
__device__ float g_h[NMAX * 64];

// ---------------------------------------------------------------------------
// Kernel 1: h = x @ weight   (x: [n,64], w: [64,64])
// Block computes 64 rows x 64 cols with 4x4 register tiles per thread.
// ---------------------------------------------------------------------------
__global__ void gemm_xw_kernel(const float* __restrict__ x,
                               const float* __restrict__ w, int n) {
    __shared__ float sw[64 * 64];      // weight, row-major [k][f]
    __shared__ float sxT[64 * 68];     // x tile transposed [k][r], pad 68

    int tid = threadIdx.x;             // 256 threads
    int row0 = blockIdx.x * 64;

    for (int i = tid; i < 4096; i += 256) sw[i] = w[i];
    for (int i = tid; i < 4096; i += 256) {
        int r = i >> 6, k = i & 63;
        int row = row0 + r;
        sxT[k * 68 + r] = (row < n) ? x[row * 64 + k] : 0.f;
    }
    __syncthreads();

    int rg = (tid & 15) * 4;   // 4 rows
    int fg = (tid >> 4) * 4;   // 4 features

    float acc[4][4] = {};
#pragma unroll
    for (int k = 0; k < 64; k++) {
        float4 xv = *(const float4*)&sxT[k * 68 + rg];
        float4 wv = *(const float4*)&sw[k * 64 + fg];
        float xr[4] = {xv.x, xv.y, xv.z, xv.w};
        float wf[4] = {wv.x, wv.y, wv.z, wv.w};
#pragma unroll
        for (int i = 0; i < 4; i++)
#pragma unroll
            for (int j = 0; j < 4; j++)
                acc[i][j] += xr[i] * wf[j];
    }

#pragma unroll
    for (int i = 0; i < 4; i++) {
        int row = row0 + rg + i;
        if (row < n) {
            float4 v = make_float4(acc[i][0], acc[i][1], acc[i][2], acc[i][3]);
            *(float4*)&g_h[row * 64 + fg] = v;
        }
    }
}

// ---------------------------------------------------------------------------
// Kernel 2: out[i][f] = bias[f]   (float4 granularity)
// ---------------------------------------------------------------------------
__global__ void init_out_kernel(float* __restrict__ out,
                                const float* __restrict__ bias, int n) {
    int i = blockIdx.x * blockDim.x + threadIdx.x;   // index in float4 units
    int total = n * 16;                              // n*64/4
    if (i < total) {
        int fq = i & 15;
        float4 b = ((const float4*)bias)[fq];
        ((float4*)out)[i] = b;
    }
}

// ---------------------------------------------------------------------------
// Kernel 3: out[row[e]] += val[e] * h[col[e]]   (16 threads per edge,
// float4 vector reduction: red.global.add.v4.f32)
// ---------------------------------------------------------------------------
__global__ void scatter_kernel(const int* __restrict__ erow,
                               const int* __restrict__ ecol,
                               const float* __restrict__ eval,
                               float* __restrict__ out, int ne) {
    long long t = (long long)blockIdx.x * blockDim.x + threadIdx.x;
    int e = (int)(t >> 4);
    int j = (int)(t & 15);
    if (e < ne) {
        int r = erow[e];
        int c = ecol[e];
        float v = eval[e];
        float4 hv = *(const float4*)&g_h[c * 64 + j * 4];
        float* p = out + (long long)r * 64 + j * 4;
        asm volatile("red.global.add.v4.f32 [%0], {%1,%2,%3,%4};"
                     :: "l"(p), "f"(v * hv.x), "f"(v * hv.y),
                        "f"(v * hv.z), "f"(v * hv.w)
                     : "memory");
    }
}

// ---------------------------------------------------------------------------
// Kernel 4: row-wise L2 normalize (one warp per row)
// ---------------------------------------------------------------------------
__global__ void norm_kernel(float* __restrict__ out, int n) {
    int warp = (blockIdx.x * blockDim.x + threadIdx.x) >> 5;
    int lane = threadIdx.x & 31;
    if (warp < n) {
        float2 v = *(float2*)&out[(long long)warp * 64 + lane * 2];
        float s = v.x * v.x + v.y * v.y;
#pragma unroll
        for (int o = 16; o > 0; o >>= 1)
            s += __shfl_xor_sync(0xffffffff, s, o);
        float inv = rsqrtf(s);
        v.x *= inv;
        v.y *= inv;
        *(float2*)&out[(long long)warp * 64 + lane * 2] = v;
    }
}

// ---------------------------------------------------------------------------
// Launch
// ---------------------------------------------------------------------------
extern "C" void kernel_launch(void* const* d_in, const int* in_sizes, int n_in,
                              void* d_out, int out_size) {
    const float* x    = (const float*)d_in[0];
    const int*   erow = (const int*)  d_in[1];
    const int*   ecol = (const int*)  d_in[2];
    const float* eval = (const float*)d_in[3];
    const float* w    = (const float*)d_in[4];
    const float* bias = (const float*)d_in[5];
    float* out = (float*)d_out;

    int n  = in_sizes[0] / 64;   // 100000 nodes
    int ne = in_sizes[1];        // 1600000 edges

    gemm_xw_kernel<<<(n + 63) / 64, 256>>>(x, w, n);
    init_out_kernel<<<(n * 16 + 255) / 256, 256>>>(out, bias, n);

    long long tot = (long long)ne * 16;
    scatter_kernel<<<(int)((tot + 255) / 256), 256>>>(erow, ecol, eval, out, ne);

    norm_kernel<<<(n * 32 + 255) / 256, 256>>>(out, n);
}

// round 4
// speedup vs baseline: 1.2010x; 1.2010x over previous
#include <cuda_runtime.h>

#define NMAX 100256
#define EMAX 1600256

// ---- static scratch (allocation-free) -------------------------------------
__device__ float g_h[NMAX * 64];        // h = X @ W
__device__ int   g_cnt[NMAX + 1];       // per-row edge counts
__device__ int   g_excl[NMAX + 1];      // block-local exclusive scan
__device__ int   g_rowptr[NMAX + 1];    // final CSR row pointers
__device__ int   g_off[NMAX + 1];       // mutable write cursors
__device__ int   g_bsum[256];           // scan block sums
__device__ int2  g_edges[EMAX];         // packed (col, val-bits) sorted by row

// ---------------------------------------------------------------------------
// Kernel 1: h = x @ weight   (x: [n,64], w: [64,64]) — 64x64 tile, 4x4 regs
// ---------------------------------------------------------------------------
__global__ void gemm_xw_kernel(const float* __restrict__ x,
                               const float* __restrict__ w, int n) {
    __shared__ float sw[64 * 64];
    __shared__ float sxT[64 * 68];

    int tid = threadIdx.x;
    int row0 = blockIdx.x * 64;

    for (int i = tid; i < 4096; i += 256) sw[i] = w[i];
    for (int i = tid; i < 4096; i += 256) {
        int r = i >> 6, k = i & 63;
        int row = row0 + r;
        sxT[k * 68 + r] = (row < n) ? x[row * 64 + k] : 0.f;
    }
    __syncthreads();

    int rg = (tid & 15) * 4;
    int fg = (tid >> 4) * 4;

    float acc[4][4] = {};
#pragma unroll
    for (int k = 0; k < 64; k++) {
        float4 xv = *(const float4*)&sxT[k * 68 + rg];
        float4 wv = *(const float4*)&sw[k * 64 + fg];
        float xr[4] = {xv.x, xv.y, xv.z, xv.w};
        float wf[4] = {wv.x, wv.y, wv.z, wv.w};
#pragma unroll
        for (int i = 0; i < 4; i++)
#pragma unroll
            for (int j = 0; j < 4; j++)
                acc[i][j] += xr[i] * wf[j];
    }

#pragma unroll
    for (int i = 0; i < 4; i++) {
        int row = row0 + rg + i;
        if (row < n)
            *(float4*)&g_h[row * 64 + fg] =
                make_float4(acc[i][0], acc[i][1], acc[i][2], acc[i][3]);
    }
}

// ---------------------------------------------------------------------------
// CSR build: zero counts -> histogram -> scan (3 kernels) -> reorder
// ---------------------------------------------------------------------------
__global__ void zero_cnt_kernel(int n) {
    int i = blockIdx.x * blockDim.x + threadIdx.x;
    if (i <= n) g_cnt[i] = 0;
}

__global__ void hist_kernel(const int* __restrict__ erow, int ne) {
    int e = blockIdx.x * blockDim.x + threadIdx.x;
    if (e < ne) atomicAdd(&g_cnt[__ldg(&erow[e])], 1);
}

// each block scans 1024 counts (256 threads x 4)
__global__ void scan1_kernel(int n) {
    __shared__ int s[256];
    int t = threadIdx.x;
    int base = blockIdx.x * 1024;
    int v[4], sum = 0;
#pragma unroll
    for (int j = 0; j < 4; j++) {
        int idx = base + t * 4 + j;
        v[j] = (idx < n) ? g_cnt[idx] : 0;
        sum += v[j];
    }
    s[t] = sum;
    __syncthreads();
    for (int off = 1; off < 256; off <<= 1) {
        int x = (t >= off) ? s[t - off] : 0;
        __syncthreads();
        if (t >= off) s[t] += x;
        __syncthreads();
    }
    int excl = s[t] - sum;
    if (t == 255) g_bsum[blockIdx.x] = s[255];
    int run = excl;
#pragma unroll
    for (int j = 0; j < 4; j++) {
        int idx = base + t * 4 + j;
        if (idx < n) g_excl[idx] = run;
        run += v[j];
    }
}

__global__ void scan2_kernel(int nb) {
    __shared__ int s[256];
    int t = threadIdx.x;
    int orig = (t < nb) ? g_bsum[t] : 0;
    s[t] = orig;
    __syncthreads();
    for (int off = 1; off < 256; off <<= 1) {
        int x = (t >= off) ? s[t - off] : 0;
        __syncthreads();
        if (t >= off) s[t] += x;
        __syncthreads();
    }
    if (t < nb) g_bsum[t] = s[t] - orig;  // exclusive block offsets
}

__global__ void scan3_kernel(int n, int ne) {
    int i = blockIdx.x * blockDim.x + threadIdx.x;
    if (i < n) {
        int p = g_excl[i] + g_bsum[i >> 10];
        g_rowptr[i] = p;
        g_off[i] = p;
    }
    if (i == 0) g_rowptr[n] = ne;
}

__global__ void reorder_kernel(const int* __restrict__ erow,
                               const int* __restrict__ ecol,
                               const float* __restrict__ eval, int ne) {
    int e = blockIdx.x * blockDim.x + threadIdx.x;
    if (e < ne) {
        int r = __ldg(&erow[e]);
        int pos = atomicAdd(&g_off[r], 1);
        g_edges[pos] = make_int2(__ldg(&ecol[e]), __float_as_int(__ldg(&eval[e])));
    }
}

// ---------------------------------------------------------------------------
// Gather + bias + L2-normalize. One warp per row; lane owns float2 of 64 feats
// ---------------------------------------------------------------------------
__global__ void gather_kernel(const float* __restrict__ bias,
                              float* __restrict__ out, int n) {
    int warp = (blockIdx.x * blockDim.x + threadIdx.x) >> 5;
    int lane = threadIdx.x & 31;
    if (warp >= n) return;

    int start = g_rowptr[warp];
    int end   = g_rowptr[warp + 1];

    float2 acc = *(const float2*)&bias[lane * 2];
    int fo = lane * 2;

    int i = start;
    // unroll-4: four independent gathers in flight before dependent FMAs
    for (; i + 4 <= end; i += 4) {
        int2 e0 = g_edges[i];
        int2 e1 = g_edges[i + 1];
        int2 e2 = g_edges[i + 2];
        int2 e3 = g_edges[i + 3];
        float2 h0 = *(const float2*)&g_h[(long long)e0.x * 64 + fo];
        float2 h1 = *(const float2*)&g_h[(long long)e1.x * 64 + fo];
        float2 h2 = *(const float2*)&g_h[(long long)e2.x * 64 + fo];
        float2 h3 = *(const float2*)&g_h[(long long)e3.x * 64 + fo];
        float v0 = __int_as_float(e0.y), v1 = __int_as_float(e1.y);
        float v2 = __int_as_float(e2.y), v3 = __int_as_float(e3.y);
        acc.x += v0 * h0.x + v1 * h1.x + v2 * h2.x + v3 * h3.x;
        acc.y += v0 * h0.y + v1 * h1.y + v2 * h2.y + v3 * h3.y;
    }
    for (; i < end; i++) {
        int2 e0 = g_edges[i];
        float2 h0 = *(const float2*)&g_h[(long long)e0.x * 64 + fo];
        float v0 = __int_as_float(e0.y);
        acc.x += v0 * h0.x;
        acc.y += v0 * h0.y;
    }

    float s = acc.x * acc.x + acc.y * acc.y;
#pragma unroll
    for (int o = 16; o > 0; o >>= 1)
        s += __shfl_xor_sync(0xffffffff, s, o);
    float inv = rsqrtf(s);

    *(float2*)&out[(long long)warp * 64 + fo] =
        make_float2(acc.x * inv, acc.y * inv);
}

// ---------------------------------------------------------------------------
extern "C" void kernel_launch(void* const* d_in, const int* in_sizes, int n_in,
                              void* d_out, int out_size) {
    const float* x    = (const float*)d_in[0];
    const int*   erow = (const int*)  d_in[1];
    const int*   ecol = (const int*)  d_in[2];
    const float* eval = (const float*)d_in[3];
    const float* w    = (const float*)d_in[4];
    const float* bias = (const float*)d_in[5];
    float* out = (float*)d_out;

    int n  = in_sizes[0] / 64;   // 100000
    int ne = in_sizes[1];        // 1600000
    int nb = (n + 1023) / 1024;  // scan blocks (<=256)

    gemm_xw_kernel<<<(n + 63) / 64, 256>>>(x, w, n);
    zero_cnt_kernel<<<(n + 256) / 256, 256>>>(n);
    hist_kernel<<<(ne + 255) / 256, 256>>>(erow, ne);
    scan1_kernel<<<nb, 256>>>(n);
    scan2_kernel<<<1, 256>>>(nb);
    scan3_kernel<<<(n + 255) / 256, 256>>>(n, ne);
    reorder_kernel<<<(ne + 255) / 256, 256>>>(erow, ecol, eval, ne);
    gather_kernel<<<(n + 7) / 8, 256>>>(bias, out, n);
}

// round 5
// speedup vs baseline: 1.2810x; 1.0667x over previous
#include <cuda_runtime.h>
#include <cuda_fp16.h>

#define NMAX 100256
#define EMAX 1600256

// ---- static scratch (allocation-free) -------------------------------------
__device__ __half2 g_h[NMAX * 32];      // h = X @ W in fp16 (row stride 32 half2)
__device__ int   g_cnt[NMAX + 1];       // per-row edge counts
__device__ int   g_excl[NMAX + 1];      // block-local exclusive scan
__device__ int   g_rowptr[NMAX + 1];    // final CSR row pointers
__device__ int   g_off[NMAX + 1];       // mutable write cursors
__device__ int   g_bsum[256];           // scan block sums
__device__ int2  g_edges[EMAX];         // packed (col, val-bits) sorted by row

// ---------------------------------------------------------------------------
// Kernel 1: h = x @ weight  (fp32 accumulate, fp16 store)
// ---------------------------------------------------------------------------
__global__ void gemm_xw_kernel(const float* __restrict__ x,
                               const float* __restrict__ w, int n) {
    __shared__ float sw[64 * 64];
    __shared__ float sxT[64 * 68];

    int tid = threadIdx.x;
    int row0 = blockIdx.x * 64;

    for (int i = tid; i < 4096; i += 256) sw[i] = w[i];
    for (int i = tid; i < 4096; i += 256) {
        int r = i >> 6, k = i & 63;
        int row = row0 + r;
        sxT[k * 68 + r] = (row < n) ? x[row * 64 + k] : 0.f;
    }
    __syncthreads();

    int rg = (tid & 15) * 4;
    int fg = (tid >> 4) * 4;

    float acc[4][4] = {};
#pragma unroll
    for (int k = 0; k < 64; k++) {
        float4 xv = *(const float4*)&sxT[k * 68 + rg];
        float4 wv = *(const float4*)&sw[k * 64 + fg];
        float xr[4] = {xv.x, xv.y, xv.z, xv.w};
        float wf[4] = {wv.x, wv.y, wv.z, wv.w};
#pragma unroll
        for (int i = 0; i < 4; i++)
#pragma unroll
            for (int j = 0; j < 4; j++)
                acc[i][j] += xr[i] * wf[j];
    }

#pragma unroll
    for (int i = 0; i < 4; i++) {
        int row = row0 + rg + i;
        if (row < n) {
            __half2 h0 = __floats2half2_rn(acc[i][0], acc[i][1]);
            __half2 h1 = __floats2half2_rn(acc[i][2], acc[i][3]);
            // fg is a multiple of 4 -> half2 index fg/2 is even, 8B aligned
            *(uint2*)&g_h[row * 32 + (fg >> 1)] =
                make_uint2(*(unsigned*)&h0, *(unsigned*)&h1);
        }
    }
}

// ---------------------------------------------------------------------------
// CSR build
// ---------------------------------------------------------------------------
__global__ void zero_cnt_kernel(int n) {
    int i = blockIdx.x * blockDim.x + threadIdx.x;
    if (i <= n) g_cnt[i] = 0;
}

__global__ void hist_kernel(const int* __restrict__ erow, int ne) {
    int e = blockIdx.x * blockDim.x + threadIdx.x;
    if (e < ne) atomicAdd(&g_cnt[__ldg(&erow[e])], 1);
}

// each block scans 1024 counts (256 threads x 4) — shuffle-based, 2 barriers
__global__ void scan1_kernel(int n) {
    __shared__ int wsum[8];
    int t = threadIdx.x;
    int lane = t & 31, wid = t >> 5;
    int base = blockIdx.x * 1024;
    int v[4], sum = 0;
#pragma unroll
    for (int j = 0; j < 4; j++) {
        int idx = base + t * 4 + j;
        v[j] = (idx < n) ? g_cnt[idx] : 0;
        sum += v[j];
    }
    // warp inclusive scan of per-thread sums
    int s = sum;
#pragma unroll
    for (int o = 1; o < 32; o <<= 1) {
        int x = __shfl_up_sync(0xffffffff, s, o);
        if (lane >= o) s += x;
    }
    if (lane == 31) wsum[wid] = s;
    __syncthreads();
    if (t < 8) {
        int wv = wsum[t];
#pragma unroll
        for (int o = 1; o < 8; o <<= 1) {
            int x = __shfl_up_sync(0xff, wv, o);
            if (t >= o) wv += x;
        }
        wsum[t] = wv;
    }
    __syncthreads();
    int incl = s + (wid ? wsum[wid - 1] : 0);
    int excl = incl - sum;
    if (t == 255) g_bsum[blockIdx.x] = incl;
    int run = excl;
#pragma unroll
    for (int j = 0; j < 4; j++) {
        int idx = base + t * 4 + j;
        if (idx < n) g_excl[idx] = run;
        run += v[j];
    }
}

__global__ void scan2_kernel(int nb) {
    __shared__ int wsum[8];
    int t = threadIdx.x;
    int lane = t & 31, wid = t >> 5;
    int orig = (t < nb) ? g_bsum[t] : 0;
    int s = orig;
#pragma unroll
    for (int o = 1; o < 32; o <<= 1) {
        int x = __shfl_up_sync(0xffffffff, s, o);
        if (lane >= o) s += x;
    }
    if (lane == 31) wsum[wid] = s;
    __syncthreads();
    if (t < 8) {
        int wv = wsum[t];
#pragma unroll
        for (int o = 1; o < 8; o <<= 1) {
            int x = __shfl_up_sync(0xff, wv, o);
            if (t >= o) wv += x;
        }
        wsum[t] = wv;
    }
    __syncthreads();
    int incl = s + (wid ? wsum[wid - 1] : 0);
    if (t < nb) g_bsum[t] = incl - orig;   // exclusive block offsets
}

__global__ void scan3_kernel(int n, int ne) {
    int i = blockIdx.x * blockDim.x + threadIdx.x;
    if (i < n) {
        int p = g_excl[i] + g_bsum[i >> 10];
        g_rowptr[i] = p;
        g_off[i] = p;
    }
    if (i == 0) g_rowptr[n] = ne;
}

__global__ void reorder_kernel(const int* __restrict__ erow,
                               const int* __restrict__ ecol,
                               const float* __restrict__ eval, int ne) {
    int e = blockIdx.x * blockDim.x + threadIdx.x;
    if (e < ne) {
        int r = __ldg(&erow[e]);
        int pos = atomicAdd(&g_off[r], 1);
        g_edges[pos] = make_int2(__ldg(&ecol[e]), __float_as_int(__ldg(&eval[e])));
    }
}

// ---------------------------------------------------------------------------
// Gather + bias + L2-normalize. One warp per row; lane owns half2 of 64 feats
// One 128B L2 line per edge per warp.
// ---------------------------------------------------------------------------
__global__ void gather_kernel(const float* __restrict__ bias,
                              float* __restrict__ out, int n) {
    int warp = (blockIdx.x * blockDim.x + threadIdx.x) >> 5;
    int lane = threadIdx.x & 31;
    if (warp >= n) return;

    int start = g_rowptr[warp];
    int end   = g_rowptr[warp + 1];

    float2 acc = *(const float2*)&bias[lane * 2];

    int i = start;
    // unroll-8: eight independent 4B gathers in flight
    for (; i + 8 <= end; i += 8) {
        float2 f[8];
        float  v[8];
#pragma unroll
        for (int j = 0; j < 8; j++) {
            int2 e = g_edges[i + j];
            __half2 hv = g_h[(long long)e.x * 32 + lane];
            f[j] = __half22float2(hv);
            v[j] = __int_as_float(e.y);
        }
#pragma unroll
        for (int j = 0; j < 8; j++) {
            acc.x += v[j] * f[j].x;
            acc.y += v[j] * f[j].y;
        }
    }
    for (; i < end; i++) {
        int2 e = g_edges[i];
        __half2 hv = g_h[(long long)e.x * 32 + lane];
        float2 f = __half22float2(hv);
        float vv = __int_as_float(e.y);
        acc.x += vv * f.x;
        acc.y += vv * f.y;
    }

    float s = acc.x * acc.x + acc.y * acc.y;
#pragma unroll
    for (int o = 16; o > 0; o >>= 1)
        s += __shfl_xor_sync(0xffffffff, s, o);
    float inv = rsqrtf(s);

    *(float2*)&out[(long long)warp * 64 + lane * 2] =
        make_float2(acc.x * inv, acc.y * inv);
}

// ---------------------------------------------------------------------------
extern "C" void kernel_launch(void* const* d_in, const int* in_sizes, int n_in,
                              void* d_out, int out_size) {
    const float* x    = (const float*)d_in[0];
    const int*   erow = (const int*)  d_in[1];
    const int*   ecol = (const int*)  d_in[2];
    const float* eval = (const float*)d_in[3];
    const float* w    = (const float*)d_in[4];
    const float* bias = (const float*)d_in[5];
    float* out = (float*)d_out;

    int n  = in_sizes[0] / 64;   // 100000
    int ne = in_sizes[1];        // 1600000
    int nb = (n + 1023) / 1024;  // scan blocks (<=98)

    gemm_xw_kernel<<<(n + 63) / 64, 256>>>(x, w, n);
    zero_cnt_kernel<<<(n + 256) / 256, 256>>>(n);
    hist_kernel<<<(ne + 255) / 256, 256>>>(erow, ne);
    scan1_kernel<<<nb, 256>>>(n);
    scan2_kernel<<<1, 256>>>(nb);
    scan3_kernel<<<(n + 255) / 256, 256>>>(n, ne);
    reorder_kernel<<<(ne + 255) / 256, 256>>>(erow, ecol, eval, ne);
    gather_kernel<<<(n + 7) / 8, 256>>>(bias, out, n);
}

// round 6
// speedup vs baseline: 1.3013x; 1.0159x over previous
#include <cuda_runtime.h>
#include <cuda_fp16.h>

#define NMAX 100256
#define EMAX 1600256

// ---- static scratch (allocation-free) -------------------------------------
__device__ __half2 g_h[NMAX * 32];      // h = X @ W in fp16 (row stride 32 half2)
__device__ int   g_cnt[NMAX + 1];       // per-row edge counts
__device__ int   g_excl[NMAX + 1];      // block-local exclusive scan
__device__ int   g_rowptr[NMAX + 1];    // final CSR row pointers
__device__ int   g_off[NMAX + 1];       // mutable write cursors
__device__ int   g_bsum[256];           // scan block sums
__device__ int2  g_edges[EMAX];         // packed (col, val-bits) sorted by row

// ---------------------------------------------------------------------------
// Kernel 1: h = x @ weight  (fp32 accumulate, fp16 store)
// ---------------------------------------------------------------------------
__global__ void gemm_xw_kernel(const float* __restrict__ x,
                               const float* __restrict__ w, int n) {
    __shared__ float sw[64 * 64];
    __shared__ float sxT[64 * 68];

    int tid = threadIdx.x;
    int row0 = blockIdx.x * 64;

    for (int i = tid; i < 4096; i += 256) sw[i] = w[i];
    for (int i = tid; i < 4096; i += 256) {
        int r = i >> 6, k = i & 63;
        int row = row0 + r;
        sxT[k * 68 + r] = (row < n) ? x[row * 64 + k] : 0.f;
    }
    __syncthreads();

    int rg = (tid & 15) * 4;
    int fg = (tid >> 4) * 4;

    float acc[4][4] = {};
#pragma unroll
    for (int k = 0; k < 64; k++) {
        float4 xv = *(const float4*)&sxT[k * 68 + rg];
        float4 wv = *(const float4*)&sw[k * 64 + fg];
        float xr[4] = {xv.x, xv.y, xv.z, xv.w};
        float wf[4] = {wv.x, wv.y, wv.z, wv.w};
#pragma unroll
        for (int i = 0; i < 4; i++)
#pragma unroll
            for (int j = 0; j < 4; j++)
                acc[i][j] += xr[i] * wf[j];
    }

#pragma unroll
    for (int i = 0; i < 4; i++) {
        int row = row0 + rg + i;
        if (row < n) {
            __half2 h0 = __floats2half2_rn(acc[i][0], acc[i][1]);
            __half2 h1 = __floats2half2_rn(acc[i][2], acc[i][3]);
            *(uint2*)&g_h[row * 32 + (fg >> 1)] =
                make_uint2(*(unsigned*)&h0, *(unsigned*)&h1);
        }
    }
}

// ---------------------------------------------------------------------------
// CSR build
// ---------------------------------------------------------------------------
__global__ void hist_kernel(const int* __restrict__ erow, int ne) {
    int e = blockIdx.x * blockDim.x + threadIdx.x;
    if (e < ne) atomicAdd(&g_cnt[__ldg(&erow[e])], 1);
}

// each block scans 1024 counts (256 threads x 4) — shuffle-based, 2 barriers
__global__ void scan1_kernel(int n) {
    __shared__ int wsum[8];
    int t = threadIdx.x;
    int lane = t & 31, wid = t >> 5;
    int base = blockIdx.x * 1024;
    int v[4], sum = 0;
#pragma unroll
    for (int j = 0; j < 4; j++) {
        int idx = base + t * 4 + j;
        v[j] = (idx < n) ? g_cnt[idx] : 0;
        sum += v[j];
    }
    int s = sum;
#pragma unroll
    for (int o = 1; o < 32; o <<= 1) {
        int x = __shfl_up_sync(0xffffffff, s, o);
        if (lane >= o) s += x;
    }
    if (lane == 31) wsum[wid] = s;
    __syncthreads();
    if (t < 8) {
        int wv = wsum[t];
#pragma unroll
        for (int o = 1; o < 8; o <<= 1) {
            int x = __shfl_up_sync(0xff, wv, o);
            if (t >= o) wv += x;
        }
        wsum[t] = wv;
    }
    __syncthreads();
    int incl = s + (wid ? wsum[wid - 1] : 0);
    int excl = incl - sum;
    if (t == 255) g_bsum[blockIdx.x] = incl;
    int run = excl;
#pragma unroll
    for (int j = 0; j < 4; j++) {
        int idx = base + t * 4 + j;
        if (idx < n) g_excl[idx] = run;
        run += v[j];
    }
}

__global__ void scan2_kernel(int nb) {
    __shared__ int wsum[8];
    int t = threadIdx.x;
    int lane = t & 31, wid = t >> 5;
    int orig = (t < nb) ? g_bsum[t] : 0;
    int s = orig;
#pragma unroll
    for (int o = 1; o < 32; o <<= 1) {
        int x = __shfl_up_sync(0xffffffff, s, o);
        if (lane >= o) s += x;
    }
    if (lane == 31) wsum[wid] = s;
    __syncthreads();
    if (t < 8) {
        int wv = wsum[t];
#pragma unroll
        for (int o = 1; o < 8; o <<= 1) {
            int x = __shfl_up_sync(0xff, wv, o);
            if (t >= o) wv += x;
        }
        wsum[t] = wv;
    }
    __syncthreads();
    int incl = s + (wid ? wsum[wid - 1] : 0);
    if (t < nb) g_bsum[t] = incl - orig;   // exclusive block offsets
}

__global__ void scan3_kernel(int n, int ne) {
    int i = blockIdx.x * blockDim.x + threadIdx.x;
    if (i < n) {
        int p = g_excl[i] + g_bsum[i >> 10];
        g_rowptr[i] = p;
        g_off[i] = p;
    }
    if (i == 0) g_rowptr[n] = ne;
}

__global__ void reorder_kernel(const int* __restrict__ erow,
                               const int* __restrict__ ecol,
                               const float* __restrict__ eval, int ne) {
    int e = blockIdx.x * blockDim.x + threadIdx.x;
    if (e < ne) {
        int r = __ldg(&erow[e]);
        int pos = atomicAdd(&g_off[r], 1);
        g_edges[pos] = make_int2(__ldg(&ecol[e]), __float_as_int(__ldg(&eval[e])));
    }
}

// ---------------------------------------------------------------------------
// Gather + bias + L2-normalize. One warp per row; lane owns half2 of 64 feats
// ---------------------------------------------------------------------------
__global__ void gather_kernel(const float* __restrict__ bias,
                              float* __restrict__ out, int n) {
    int warp = (blockIdx.x * blockDim.x + threadIdx.x) >> 5;
    int lane = threadIdx.x & 31;
    if (warp >= n) return;

    int start = g_rowptr[warp];
    int end   = g_rowptr[warp + 1];

    float2 acc = *(const float2*)&bias[lane * 2];

    int i = start;
    for (; i + 8 <= end; i += 8) {
        float2 f[8];
        float  v[8];
#pragma unroll
        for (int j = 0; j < 8; j++) {
            int2 e = g_edges[i + j];
            __half2 hv = g_h[(long long)e.x * 32 + lane];
            f[j] = __half22float2(hv);
            v[j] = __int_as_float(e.y);
        }
#pragma unroll
        for (int j = 0; j < 8; j++) {
            acc.x += v[j] * f[j].x;
            acc.y += v[j] * f[j].y;
        }
    }
    for (; i < end; i++) {
        int2 e = g_edges[i];
        __half2 hv = g_h[(long long)e.x * 32 + lane];
        float2 f = __half22float2(hv);
        float vv = __int_as_float(e.y);
        acc.x += vv * f.x;
        acc.y += vv * f.y;
    }

    float s = acc.x * acc.x + acc.y * acc.y;
#pragma unroll
    for (int o = 16; o > 0; o >>= 1)
        s += __shfl_xor_sync(0xffffffff, s, o);
    float inv = rsqrtf(s);

    *(float2*)&out[(long long)warp * 64 + lane * 2] =
        make_float2(acc.x * inv, acc.y * inv);
}

// ---------------------------------------------------------------------------
// Launch: fork GEMM (main stream) parallel to CSR build (side stream), join
// before gather. Event fork/join is the standard graph-capture pattern.
// ---------------------------------------------------------------------------
extern "C" void kernel_launch(void* const* d_in, const int* in_sizes, int n_in,
                              void* d_out, int out_size) {
    const float* x    = (const float*)d_in[0];
    const int*   erow = (const int*)  d_in[1];
    const int*   ecol = (const int*)  d_in[2];
    const float* eval = (const float*)d_in[3];
    const float* w    = (const float*)d_in[4];
    const float* bias = (const float*)d_in[5];
    float* out = (float*)d_out;

    int n  = in_sizes[0] / 64;   // 100000
    int ne = in_sizes[1];        // 1600000
    int nb = (n + 1023) / 1024;  // scan blocks (<=98)

    static cudaStream_t sB = nullptr;
    static cudaEvent_t evFork = nullptr, evJoin = nullptr;
    static void* cnt_ptr = nullptr;
    if (sB == nullptr) {
        cudaStreamCreateWithFlags(&sB, cudaStreamNonBlocking);
        cudaEventCreateWithFlags(&evFork, cudaEventDisableTiming);
        cudaEventCreateWithFlags(&evJoin, cudaEventDisableTiming);
        cudaGetSymbolAddress(&cnt_ptr, g_cnt);
    }

    // fork: side stream joins the capture via event wait
    cudaEventRecord(evFork, 0);
    cudaStreamWaitEvent(sB, evFork, 0);

    // branch B: CSR build
    cudaMemsetAsync(cnt_ptr, 0, (size_t)(n + 1) * sizeof(int), sB);
    hist_kernel<<<(ne + 255) / 256, 256, 0, sB>>>(erow, ne);
    scan1_kernel<<<nb, 256, 0, sB>>>(n);
    scan2_kernel<<<1, 256, 0, sB>>>(nb);
    scan3_kernel<<<(n + 255) / 256, 256, 0, sB>>>(n, ne);
    reorder_kernel<<<(ne + 255) / 256, 256, 0, sB>>>(erow, ecol, eval, ne);
    cudaEventRecord(evJoin, sB);

    // branch A (main): dense GEMM
    gemm_xw_kernel<<<(n + 63) / 64, 256>>>(x, w, n);

    // join, then gather
    cudaStreamWaitEvent(0, evJoin, 0);
    gather_kernel<<<(n + 7) / 8, 256>>>(bias, out, n);
}